// round 9
// baseline (speedup 1.0000x reference)
#include <cuda_runtime.h>
#include <cuda_bf16.h>
#include <cuda_fp16.h>
#include <math.h>
#include <stdint.h>

#define NB 256   // batch
#define NL 128   // seq len
#define NC 256   // input channels
#define NH 512   // hidden
#define NG 2048  // 4*H

__device__ __forceinline__ uint32_t smem_u32_of(const void* p) {
    uint32_t a;
    asm("{ .reg .u64 t; cvta.to.shared.u64 t, %1; cvt.u32.u64 %0, t; }" : "=r"(a) : "l"(p));
    return a;
}

// ===================== device globals (no allocation allowed) ===============
__device__ float g_Wp[(size_t)NH * NG];               // W' = Wmh@Whm (fp32)
__device__ float g_Wb[(size_t)NC * NG];               // Wbig = Wih + Wmx@Whm
__device__ float g_bvp[NG];                           // folded bias, permuted cols
__device__ __half g_Wp16[(size_t)NG * NH];            // fp16(W'^T) permuted [n'][512]
__device__ __half g_Wb16[(size_t)NG * NC];            // fp16(Wbig^T) perm [n'][256]
__device__ __half g_x16[(size_t)NB * NL * NC];        // fp16(x) [m][256]
__device__ __half g_h16[2][(size_t)NB * NH];          // hidden fp16, ping-pong
__device__ float g_P[(size_t)NL * NB * NG];           // TIME-MAJOR: [t][b][n']
// cell state lives in registers inside the persistent scan kernel

// ===================== prep kernels =========================================
__global__ void init_state_kernel() {
    int i = blockIdx.x * blockDim.x + threadIdx.x;
    if (i < NB * NH) g_h16[0][i] = __float2half_rn(0.f);
    if (i < NG) g_bvp[i] = 0.f;
}

__device__ __forceinline__ int perm_col(int n) {       // natural gate col -> permuted
    int j = n & 511, g = n >> 9;
    return ((j >> 3) << 5) | (g << 3) | (j & 7);
}

// split-K bvec: grid (8 n-blocks, 8 k-slices), atomicAdd into zeroed g_bvp
__global__ void bvec_kernel(const float* __restrict__ bih, const float* __restrict__ bhm,
                            const float* __restrict__ bmx, const float* __restrict__ bmh,
                            const float* __restrict__ Whm) {
    int n = blockIdx.x * blockDim.x + threadIdx.x;
    int k0 = blockIdx.y * 64;
    float acc[8] = {};
    for (int kk = 0; kk < 64; kk += 8) {
#pragma unroll
        for (int u = 0; u < 8; u++) {
            int k = k0 + kk + u;
            acc[u] = fmaf(bmx[k] + bmh[k], Whm[(size_t)k * NG + n], acc[u]);
        }
    }
    float s = (blockIdx.y == 0) ? (bih[n] + bhm[n]) : 0.f;
#pragma unroll
    for (int u = 0; u < 8; u++) s += acc[u];
    atomicAdd(&g_bvp[perm_col(n)], s);
}

// fp32 SIMT GEMM for small weight prep
template <bool HASC>
__global__ __launch_bounds__(256)
void gemm64(const float* __restrict__ A, const float* __restrict__ Bm,
            const float* __restrict__ Cadd, float* __restrict__ Out,
            int M, int N, int K) {
    __shared__ float sA[16][64];
    __shared__ float sB[16][64];
    const int bm = blockIdx.y * 64, bn = blockIdx.x * 64;
    const int tid  = threadIdx.x;
    const int arow = tid >> 2, akq = tid & 3;
    const int brow = tid >> 4, bnq = tid & 15;
    const int tr   = tid >> 4, tcx = tid & 15;
    float acc[4][4] = {};
    for (int k0 = 0; k0 < K; k0 += 16) {
        float4 av = *reinterpret_cast<const float4*>(A + (size_t)(bm + arow) * K + k0 + akq * 4);
        float4 bv = *reinterpret_cast<const float4*>(Bm + (size_t)(k0 + brow) * N + bn + bnq * 4);
        __syncthreads();
        sA[akq * 4 + 0][arow] = av.x; sA[akq * 4 + 1][arow] = av.y;
        sA[akq * 4 + 2][arow] = av.z; sA[akq * 4 + 3][arow] = av.w;
        *reinterpret_cast<float4*>(&sB[brow][bnq * 4]) = bv;
        __syncthreads();
#pragma unroll
        for (int k = 0; k < 16; k++) {
            float4 a = *reinterpret_cast<float4*>(&sA[k][tr * 4]);
            float4 b = *reinterpret_cast<float4*>(&sB[k][tcx * 4]);
            float aa[4] = {a.x, a.y, a.z, a.w};
            float bb[4] = {b.x, b.y, b.z, b.w};
#pragma unroll
            for (int i = 0; i < 4; i++)
#pragma unroll
                for (int j = 0; j < 4; j++)
                    acc[i][j] = fmaf(aa[i], bb[j], acc[i][j]);
        }
    }
#pragma unroll
    for (int i = 0; i < 4; i++) {
        int m = bm + tr * 4 + i, n = bn + tcx * 4;
        float4 r = make_float4(acc[i][0], acc[i][1], acc[i][2], acc[i][3]);
        if (HASC) {
            float4 c = *reinterpret_cast<const float4*>(Cadd + (size_t)m * N + n);
            r.x += c.x; r.y += c.y; r.z += c.z; r.w += c.w;
        }
        *reinterpret_cast<float4*>(Out + (size_t)m * N + n) = r;
    }
}

// transpose + permute -> fp16 [2048 perm][ldd]
__global__ void wsplit16_kernel(const float* __restrict__ src,
                                __half* __restrict__ dst, int ldd) {
    __shared__ float sA[32][33];
    const int n0 = blockIdx.x * 32, k0 = blockIdx.y * 32;
    const int t = threadIdx.x;
    {
        int nl = t & 31, rr = t >> 5;
#pragma unroll
        for (int it = 0; it < 4; it++) {
            int kl = it * 8 + rr;
            sA[kl][nl] = src[(size_t)(k0 + kl) * NG + n0 + nl];
        }
    }
    __syncthreads();
    int nlo = t >> 3, ks = t & 7;
    int np = perm_col(n0 + nlo);
    union { __half h[4]; uint2 u; } H;
#pragma unroll
    for (int kk = 0; kk < 4; kk++)
        H.h[kk] = __float2half_rn(sA[ks * 4 + kk][nlo]);
    *reinterpret_cast<uint2*>(dst + (size_t)np * ldd + k0 + ks * 4) = H.u;
}

// x fp32 -> fp16 (elementwise)
__global__ void xsplit_kernel(const float* __restrict__ x) {
    size_t i = (size_t)blockIdx.x * blockDim.x + threadIdx.x;  // float4 index
    float4 v = reinterpret_cast<const float4*>(x)[i];
    union { __half h[4]; uint2 u; } H;
    H.h[0] = __float2half_rn(v.x); H.h[1] = __float2half_rn(v.y);
    H.h[2] = __float2half_rn(v.z); H.h[3] = __float2half_rn(v.w);
    reinterpret_cast<uint2*>(g_x16)[i] = H.u;
}

// ===================== P GEMM (HMMA fp16, Kc=256, time-major P out) =========
__global__ __launch_bounds__(256)
void pgemm_mma(const __half* __restrict__ A, const __half* __restrict__ Bw, int Kc) {
    constexpr int BM = 128, BN = 128, WN_ = 4, MF = 4;
    __shared__ __half sA[2][BM][40];
    __shared__ __half sB[2][BN][40];
    const int tid = threadIdx.x, lane = tid & 31, w = tid >> 5;
    const int wn0 = (w % WN_) * 32, wm0 = (w / WN_) * 64;
    const int m0 = blockIdx.y * BM, n0 = blockIdx.x * BN;

    auto load_stage = [&](int s, int k0) {
#pragma unroll
        for (int i = 0; i < (BM + BN) * 4 / 256; i++) {
            int q = i * 256 + tid;
            const __half* src;
            uint32_t dst;
            if (q < BM * 4) {
                int r = q >> 2, c = q & 3;
                src = A + (size_t)(m0 + r) * Kc + k0 + c * 8;
                dst = smem_u32_of(&sA[s][r][c * 8]);
            } else {
                int q2 = q - BM * 4, r = q2 >> 2, c = q2 & 3;
                src = Bw + (size_t)(n0 + r) * Kc + k0 + c * 8;
                dst = smem_u32_of(&sB[s][r][c * 8]);
            }
            asm volatile("cp.async.cg.shared.global [%0], [%1], 16;" :: "r"(dst), "l"(src));
        }
        asm volatile("cp.async.commit_group;");
    };

    float acc[MF][4][4] = {};
    const int arow = (lane & 7) + ((lane >> 3) & 1) * 8;
    const int akm  = (lane >> 4) & 1;
    const int brow = lane & 7;
    const int bkm  = (lane >> 3) & 1;

    const int NIT = Kc >> 5;
    load_stage(0, 0);
    for (int it = 0; it < NIT; it++) {
        if (it + 1 < NIT) {
            load_stage((it + 1) & 1, (it + 1) * 32);
            asm volatile("cp.async.wait_group 1;");
        } else {
            asm volatile("cp.async.wait_group 0;");
        }
        __syncthreads();
        int s = it & 1;
#pragma unroll
        for (int ks = 0; ks < 2; ks++) {
            uint32_t aR[MF][4], bR[4][2];
#pragma unroll
            for (int ni = 0; ni < 4; ni++) {
                uint32_t ad = smem_u32_of(&sB[s][wn0 + ni * 8 + brow][ks * 16 + bkm * 8]);
                asm volatile("ldmatrix.sync.aligned.m8n8.x2.shared.b16 {%0,%1}, [%2];"
                             : "=r"(bR[ni][0]), "=r"(bR[ni][1]) : "r"(ad));
            }
#pragma unroll
            for (int mi = 0; mi < MF; mi++) {
                uint32_t ad = smem_u32_of(&sA[s][wm0 + mi * 16 + arow][ks * 16 + akm * 8]);
                asm volatile("ldmatrix.sync.aligned.m8n8.x4.shared.b16 {%0,%1,%2,%3}, [%4];"
                             : "=r"(aR[mi][0]), "=r"(aR[mi][1]), "=r"(aR[mi][2]), "=r"(aR[mi][3])
                             : "r"(ad));
            }
#pragma unroll
            for (int mi = 0; mi < MF; mi++)
#pragma unroll
                for (int ni = 0; ni < 4; ni++)
                    asm volatile(
                        "mma.sync.aligned.m16n8k16.row.col.f32.f16.f16.f32 "
                        "{%0,%1,%2,%3}, {%4,%5,%6,%7}, {%8,%9}, {%0,%1,%2,%3};"
                        : "+f"(acc[mi][ni][0]), "+f"(acc[mi][ni][1]),
                          "+f"(acc[mi][ni][2]), "+f"(acc[mi][ni][3])
                        : "r"(aR[mi][0]), "r"(aR[mi][1]), "r"(aR[mi][2]), "r"(aR[mi][3]),
                          "r"(bR[ni][0]), "r"(bR[ni][1]));
        }
        __syncthreads();
    }
#pragma unroll
    for (int mi = 0; mi < MF; mi++) {
#pragma unroll
        for (int half = 0; half < 2; half++) {
            int r = m0 + wm0 + mi * 16 + (lane >> 2) + half * 8;
            size_t dr = (size_t)(r & (NL - 1)) * NB + (size_t)(r >> 7);
#pragma unroll
            for (int ni = 0; ni < 4; ni++) {
                int col = n0 + wn0 + ni * 8 + (lane & 3) * 2;
                *reinterpret_cast<float2*>(&g_P[dr * NG + col]) =
                    make_float2(acc[mi][ni][half * 2 + 0] + g_bvp[col],
                                acc[mi][ni][half * 2 + 1] + g_bvp[col + 1]);
            }
        }
    }
}

// ===================== persistent scan kernel (16-CTA clusters) =============
// grid (16 n-tiles of 128, 8 m-groups of 32). One cluster per m-group.
// B tile (128 x 512 fp16) resident in SMEM; barrier = cluster.sync.
static constexpr int SBP = 520;                        // halves (1040 B pitch)
static constexpr int SAP = 136;                        // halves (272 B pitch)
static constexpr int SA_STAGE = 32 * SAP;
static constexpr int SCAN_SMEM = (128 * SBP + 4 * SA_STAGE) * 2;   // 167,936 B

__device__ __forceinline__ void wait_grp(int n) {
    switch (n) {
        case 0: asm volatile("cp.async.wait_group 0;" ::: "memory"); break;
        case 1: asm volatile("cp.async.wait_group 1;" ::: "memory"); break;
        case 2: asm volatile("cp.async.wait_group 2;" ::: "memory"); break;
        default: asm volatile("cp.async.wait_group 3;" ::: "memory"); break;
    }
}

__global__ __launch_bounds__(256) __cluster_dims__(16, 1, 1)
void scan_kernel(float* __restrict__ out) {
    extern __shared__ __half sm16[];
    __half* sB = sm16;                                // [128][520]
    __half* sA = sm16 + 128 * SBP;                    // [4][32][136]
    const int tid = threadIdx.x, lane = tid & 31, w = tid >> 5;
    const int n0 = blockIdx.x * 128, m0 = blockIdx.y * 32;
    const int wn0 = (w & 3) * 32, wm0 = (w >> 2) * 16;

    // ---- resident B tile: W1 rows n0..n0+127, 512 cols ---------------------
#pragma unroll
    for (int i = 0; i < 32; i++) {
        int q = i * 256 + tid;                        // 8192 16B-chunks
        int r = q >> 6, cc = q & 63;
        asm volatile("cp.async.cg.shared.global [%0], [%1], 16;"
                     :: "r"(smem_u32_of(sB + r * SBP + cc * 8)),
                        "l"(g_Wp16 + (size_t)(n0 + r) * NH + cc * 8));
    }
    asm volatile("cp.async.commit_group;");
    asm volatile("cp.async.wait_group 0;");
    __syncthreads();

    const int arow = (lane & 7) + ((lane >> 3) & 1) * 8;
    const int akm  = (lane >> 4) & 1;
    const int browB = ((lane >> 4) & 1) * 8 + (lane & 7);
    const int bkmB  = (lane >> 3) & 1;
    const int p0 = (lane & 3) * 2;
    const int j = ((n0 + wn0) >> 5) * 8 + p0;         // hidden unit (even)

    float creg[2][2] = {};                            // cell state in registers
    float2 pv[2][4];                                  // prefetched P

    auto loadP = [&](int tt) {
        const float* Pt = g_P + (size_t)tt * NB * NG;
#pragma unroll
        for (int half = 0; half < 2; half++) {
            int b = m0 + wm0 + (lane >> 2) + half * 8;
#pragma unroll
            for (int ni = 0; ni < 4; ni++)
                pv[half][ni] = __ldg(reinterpret_cast<const float2*>(
                    Pt + (size_t)b * NG + n0 + wn0 + ni * 8 + p0));
        }
    };
    loadP(0);

    for (int t = 0; t < NL; t++) {
        const int par = t & 1;
        const __half* hsrc = g_h16[par];

        // issue ALL 4 A chunks (8 KB each)
#pragma unroll
        for (int c = 0; c < 4; c++) {
#pragma unroll
            for (int i = 0; i < 2; i++) {
                int q = i * 256 + tid;
                int r = q >> 4, cc = q & 15;
                asm volatile("cp.async.cg.shared.global [%0], [%1], 16;"
                             :: "r"(smem_u32_of(sA + c * SA_STAGE + r * SAP + cc * 8)),
                                "l"(hsrc + (size_t)(m0 + r) * NH + c * 128 + cc * 8));
            }
            asm volatile("cp.async.commit_group;");
        }

        float acc[4][4] = {};
#pragma unroll
        for (int c = 0; c < 4; c++) {
            wait_grp(3 - c);
            __syncthreads();
            const __half* As = sA + c * SA_STAGE;
            const int kb = c * 128;
#pragma unroll
            for (int ks = 0; ks < 8; ks++) {
                uint32_t aR[4];
                asm volatile("ldmatrix.sync.aligned.m8n8.x4.shared.b16 {%0,%1,%2,%3}, [%4];"
                             : "=r"(aR[0]), "=r"(aR[1]), "=r"(aR[2]), "=r"(aR[3])
                             : "r"(smem_u32_of(As + (wm0 + arow) * SAP + ks * 16 + akm * 8)));
#pragma unroll
                for (int p = 0; p < 2; p++) {
                    uint32_t b4[4];
                    asm volatile("ldmatrix.sync.aligned.m8n8.x4.shared.b16 {%0,%1,%2,%3}, [%4];"
                                 : "=r"(b4[0]), "=r"(b4[1]), "=r"(b4[2]), "=r"(b4[3])
                                 : "r"(smem_u32_of(sB + (wn0 + p * 16 + browB) * SBP
                                                   + kb + ks * 16 + bkmB * 8)));
                    asm volatile(
                        "mma.sync.aligned.m16n8k16.row.col.f32.f16.f16.f32 "
                        "{%0,%1,%2,%3}, {%4,%5,%6,%7}, {%8,%9}, {%0,%1,%2,%3};"
                        : "+f"(acc[2 * p][0]), "+f"(acc[2 * p][1]),
                          "+f"(acc[2 * p][2]), "+f"(acc[2 * p][3])
                        : "r"(aR[0]), "r"(aR[1]), "r"(aR[2]), "r"(aR[3]),
                          "r"(b4[0]), "r"(b4[1]));
                    asm volatile(
                        "mma.sync.aligned.m16n8k16.row.col.f32.f16.f16.f32 "
                        "{%0,%1,%2,%3}, {%4,%5,%6,%7}, {%8,%9}, {%0,%1,%2,%3};"
                        : "+f"(acc[2 * p + 1][0]), "+f"(acc[2 * p + 1][1]),
                          "+f"(acc[2 * p + 1][2]), "+f"(acc[2 * p + 1][3])
                        : "r"(aR[0]), "r"(aR[1]), "r"(aR[2]), "r"(aR[3]),
                          "r"(b4[2]), "r"(b4[3]));
                }
            }
        }

        // ---- fused LSTM pointwise epilogue (cell state in registers) -------
        __half* hdst = g_h16[par ^ 1];
#pragma unroll
        for (int half = 0; half < 2; half++) {
            int b = m0 + wm0 + (lane >> 2) + half * 8;
            float hn[2], cn[2];
#pragma unroll
            for (int e = 0; e < 2; e++) {
                int a = half * 2 + e;
                float iv = acc[0][a] + (e ? pv[half][0].y : pv[half][0].x);
                float fv = acc[1][a] + (e ? pv[half][1].y : pv[half][1].x);
                float gv = acc[2][a] + (e ? pv[half][2].y : pv[half][2].x);
                float ov = acc[3][a] + (e ? pv[half][3].y : pv[half][3].x);
                float si = 1.f / (1.f + expf(-iv));
                float sf = 1.f / (1.f + expf(-fv));
                float so = 1.f / (1.f + expf(-ov));
                float tg = tanhf(gv);
                float Cn = sf * creg[half][e] + si * tg;
                creg[half][e] = Cn;
                cn[e] = Cn;
                hn[e] = so * tanhf(Cn);
            }
            size_t o = (size_t)b * (NL * NH) + (size_t)t * NH + j;
            *reinterpret_cast<float2*>(&out[o]) = make_float2(hn[0], hn[1]);
            *reinterpret_cast<float2*>(&out[o + (size_t)NB * NL * NH]) = make_float2(cn[0], cn[1]);
            *reinterpret_cast<__half2*>(hdst + (size_t)b * NH + j) =
                __halves2half2(__float2half_rn(hn[0]), __float2half_rn(hn[1]));
        }

        // prefetch P for next step — overlaps fence + cluster barrier
        if (t + 1 < NL) loadP(t + 1);

        // ---- cluster barrier (orders global h writes cluster-wide) --------
        asm volatile("fence.acq_rel.cluster;" ::: "memory");
        asm volatile("barrier.cluster.arrive.aligned;" ::: "memory");
        asm volatile("barrier.cluster.wait.aligned;" ::: "memory");
        asm volatile("fence.acq_rel.cluster;" ::: "memory");
    }
}

// ===================== x_tilde ==============================================
__global__ void xtilde_kernel(const float* __restrict__ x, const float* __restrict__ Wa,
                              const float* __restrict__ ba, float* __restrict__ out) {
    __shared__ float red[NC];
    __shared__ float s_wa[NL];
    int b = blockIdx.x, c = threadIdx.x;
    if (c < NL) s_wa[c] = Wa[2 * NH + c];
    __syncthreads();
    const float* xb = x + (size_t)b * NL * NC;
    float s = ba[0];
#pragma unroll 4
    for (int l = 0; l < NL; l++) s = fmaf(xb[(size_t)l * NC + c], s_wa[l], s);
    red[c] = s; __syncthreads();
    for (int o = NC / 2; o > 0; o >>= 1) { if (c < o) red[c] = fmaxf(red[c], red[c + o]); __syncthreads(); }
    float mx = red[0]; __syncthreads();
    float e = expf(s - mx);
    red[c] = e; __syncthreads();
    for (int o = NC / 2; o > 0; o >>= 1) { if (c < o) red[c] += red[c + o]; __syncthreads(); }
    float alpha = e / red[0];
    float* ob = out + (size_t)b * NL * NC;
#pragma unroll 4
    for (int l = 0; l < NL; l++) ob[(size_t)l * NC + c] = alpha * xb[(size_t)l * NC + c];
}

// ===================== host =================================================
extern "C" void kernel_launch(void* const* d_in, const int* in_sizes, int n_in,
                              void* d_out, int out_size) {
    const float* x   = (const float*)d_in[0];
    const float* Wih = (const float*)d_in[1];
    const float* bih = (const float*)d_in[2];
    const float* Wmx = (const float*)d_in[3];
    const float* bmx = (const float*)d_in[4];
    const float* Wmh = (const float*)d_in[5];
    const float* bmh = (const float*)d_in[6];
    const float* Whm = (const float*)d_in[7];
    const float* bhm = (const float*)d_in[8];
    const float* Wa  = (const float*)d_in[9];
    const float* ba  = (const float*)d_in[10];
    float* out = (float*)d_out;

    float *pWp, *pWb;
    __half *pWp16, *pWb16, *pX16;
    cudaGetSymbolAddress((void**)&pWp,   g_Wp);
    cudaGetSymbolAddress((void**)&pWb,   g_Wb);
    cudaGetSymbolAddress((void**)&pWp16, g_Wp16);
    cudaGetSymbolAddress((void**)&pWb16, g_Wb16);
    cudaGetSymbolAddress((void**)&pX16,  g_x16);

    cudaFuncSetAttribute(scan_kernel, cudaFuncAttributeMaxDynamicSharedMemorySize, SCAN_SMEM);
    cudaFuncSetAttribute(scan_kernel, cudaFuncAttributeNonPortableClusterSizeAllowed, 1);

    init_state_kernel<<<(NB * NH + 255) / 256, 256>>>();

    // folded weights (fp32 SIMT — small)
    gemm64<false><<<dim3(NG / 64, NH / 64), 256>>>(Wmh, Whm, nullptr, pWp, NH, NG, NH);
    gemm64<true ><<<dim3(NG / 64, NC / 64), 256>>>(Wmx, Whm, Wih, pWb, NC, NG, NH);
    bvec_kernel<<<dim3(8, 8), 256>>>(bih, bhm, bmx, bmh, Whm);

    // weight / x conversions to fp16
    wsplit16_kernel<<<dim3(NG / 32, NH / 32), 256>>>(pWp, pWp16, NH);
    wsplit16_kernel<<<dim3(NG / 32, NC / 32), 256>>>(pWb, pWb16, NC);
    xsplit_kernel<<<(NB * NL * NC / 4) / 256, 256>>>(x);

    // P = x @ Wbig + bias  (HMMA fp16, Kc=256, time-major output)
    pgemm_mma<<<dim3(NG / 128, (NB * NL) / 128), 256>>>(pX16, pWb16, NC);

    // x_tilde (softmax over c is time-invariant)
    xtilde_kernel<<<NB, 256>>>(x, Wa, ba, out + (size_t)2 * NB * NL * NH);

    // persistent fused scan: 8 independent 16-CTA clusters, cluster.sync/step
    scan_kernel<<<dim3(16, 8), 256, SCAN_SMEM>>>(out);
}

// round 10
// speedup vs baseline: 1.5646x; 1.5646x over previous
#include <cuda_runtime.h>
#include <cuda_bf16.h>
#include <cuda_fp16.h>
#include <math.h>
#include <stdint.h>

#define NB 256   // batch
#define NL 128   // seq len
#define NC 256   // input channels
#define NH 512   // hidden
#define NG 2048  // 4*H

__device__ __forceinline__ uint32_t smem_u32_of(const void* p) {
    uint32_t a;
    asm("{ .reg .u64 t; cvta.to.shared.u64 t, %1; cvt.u32.u64 %0, t; }" : "=r"(a) : "l"(p));
    return a;
}

// ===================== device globals (no allocation allowed) ===============
__device__ float g_Wp[(size_t)NH * NG];               // W' = Wmh@Whm (fp32)
__device__ float g_Wb[(size_t)NC * NG];               // Wbig = Wih + Wmx@Whm
__device__ float g_bvp[NG];                           // folded bias, permuted cols
__device__ __half g_Wp16[(size_t)NG * NH];            // fp16(W'^T) permuted [n'][512]
__device__ __half g_Wb16[(size_t)NG * NC];            // fp16(Wbig^T) perm [n'][256]
__device__ __half g_x16[(size_t)NB * NL * NC];        // fp16(x) [m][256]
__device__ __half g_h16[2][(size_t)NB * NH];          // hidden fp16, ping-pong
__device__ float g_P[(size_t)NL * NB * NG];           // TIME-MAJOR: [t][b][n']
__device__ int   g_bar[4];                            // per-m-group barrier counters
// cell state lives in registers inside the persistent scan kernel

// ===================== prep kernels =========================================
__global__ void init_state_kernel() {
    int i = blockIdx.x * blockDim.x + threadIdx.x;
    if (i < NB * NH) g_h16[0][i] = __float2half_rn(0.f);
    if (i < NG) g_bvp[i] = 0.f;
    if (i < 4) g_bar[i] = 0;
}

__device__ __forceinline__ int perm_col(int n) {       // natural gate col -> permuted
    int j = n & 511, g = n >> 9;
    return ((j >> 3) << 5) | (g << 3) | (j & 7);
}

// split-K bvec: grid (8 n-blocks, 8 k-slices), atomicAdd into zeroed g_bvp
__global__ void bvec_kernel(const float* __restrict__ bih, const float* __restrict__ bhm,
                            const float* __restrict__ bmx, const float* __restrict__ bmh,
                            const float* __restrict__ Whm) {
    int n = blockIdx.x * blockDim.x + threadIdx.x;
    int k0 = blockIdx.y * 64;
    float acc[8] = {};
    for (int kk = 0; kk < 64; kk += 8) {
#pragma unroll
        for (int u = 0; u < 8; u++) {
            int k = k0 + kk + u;
            acc[u] = fmaf(bmx[k] + bmh[k], Whm[(size_t)k * NG + n], acc[u]);
        }
    }
    float s = (blockIdx.y == 0) ? (bih[n] + bhm[n]) : 0.f;
#pragma unroll
    for (int u = 0; u < 8; u++) s += acc[u];
    atomicAdd(&g_bvp[perm_col(n)], s);
}

// fp32 SIMT GEMM for small weight prep
template <bool HASC>
__global__ __launch_bounds__(256)
void gemm64(const float* __restrict__ A, const float* __restrict__ Bm,
            const float* __restrict__ Cadd, float* __restrict__ Out,
            int M, int N, int K) {
    __shared__ float sA[16][64];
    __shared__ float sB[16][64];
    const int bm = blockIdx.y * 64, bn = blockIdx.x * 64;
    const int tid  = threadIdx.x;
    const int arow = tid >> 2, akq = tid & 3;
    const int brow = tid >> 4, bnq = tid & 15;
    const int tr   = tid >> 4, tcx = tid & 15;
    float acc[4][4] = {};
    for (int k0 = 0; k0 < K; k0 += 16) {
        float4 av = *reinterpret_cast<const float4*>(A + (size_t)(bm + arow) * K + k0 + akq * 4);
        float4 bv = *reinterpret_cast<const float4*>(Bm + (size_t)(k0 + brow) * N + bn + bnq * 4);
        __syncthreads();
        sA[akq * 4 + 0][arow] = av.x; sA[akq * 4 + 1][arow] = av.y;
        sA[akq * 4 + 2][arow] = av.z; sA[akq * 4 + 3][arow] = av.w;
        *reinterpret_cast<float4*>(&sB[brow][bnq * 4]) = bv;
        __syncthreads();
#pragma unroll
        for (int k = 0; k < 16; k++) {
            float4 a = *reinterpret_cast<float4*>(&sA[k][tr * 4]);
            float4 b = *reinterpret_cast<float4*>(&sB[k][tcx * 4]);
            float aa[4] = {a.x, a.y, a.z, a.w};
            float bb[4] = {b.x, b.y, b.z, b.w};
#pragma unroll
            for (int i = 0; i < 4; i++)
#pragma unroll
                for (int j = 0; j < 4; j++)
                    acc[i][j] = fmaf(aa[i], bb[j], acc[i][j]);
        }
    }
#pragma unroll
    for (int i = 0; i < 4; i++) {
        int m = bm + tr * 4 + i, n = bn + tcx * 4;
        float4 r = make_float4(acc[i][0], acc[i][1], acc[i][2], acc[i][3]);
        if (HASC) {
            float4 c = *reinterpret_cast<const float4*>(Cadd + (size_t)m * N + n);
            r.x += c.x; r.y += c.y; r.z += c.z; r.w += c.w;
        }
        *reinterpret_cast<float4*>(Out + (size_t)m * N + n) = r;
    }
}

// transpose + permute -> fp16 [2048 perm][ldd]
__global__ void wsplit16_kernel(const float* __restrict__ src,
                                __half* __restrict__ dst, int ldd) {
    __shared__ float sA[32][33];
    const int n0 = blockIdx.x * 32, k0 = blockIdx.y * 32;
    const int t = threadIdx.x;
    {
        int nl = t & 31, rr = t >> 5;
#pragma unroll
        for (int it = 0; it < 4; it++) {
            int kl = it * 8 + rr;
            sA[kl][nl] = src[(size_t)(k0 + kl) * NG + n0 + nl];
        }
    }
    __syncthreads();
    int nlo = t >> 3, ks = t & 7;
    int np = perm_col(n0 + nlo);
    union { __half h[4]; uint2 u; } H;
#pragma unroll
    for (int kk = 0; kk < 4; kk++)
        H.h[kk] = __float2half_rn(sA[ks * 4 + kk][nlo]);
    *reinterpret_cast<uint2*>(dst + (size_t)np * ldd + k0 + ks * 4) = H.u;
}

// x fp32 -> fp16 (elementwise)
__global__ void xsplit_kernel(const float* __restrict__ x) {
    size_t i = (size_t)blockIdx.x * blockDim.x + threadIdx.x;  // float4 index
    float4 v = reinterpret_cast<const float4*>(x)[i];
    union { __half h[4]; uint2 u; } H;
    H.h[0] = __float2half_rn(v.x); H.h[1] = __float2half_rn(v.y);
    H.h[2] = __float2half_rn(v.z); H.h[3] = __float2half_rn(v.w);
    reinterpret_cast<uint2*>(g_x16)[i] = H.u;
}

// ===================== P GEMM (HMMA fp16, Kc=256, time-major P out) =========
__global__ __launch_bounds__(256)
void pgemm_mma(const __half* __restrict__ A, const __half* __restrict__ Bw, int Kc) {
    constexpr int BM = 128, BN = 128, WN_ = 4, MF = 4;
    __shared__ __half sA[2][BM][40];
    __shared__ __half sB[2][BN][40];
    const int tid = threadIdx.x, lane = tid & 31, w = tid >> 5;
    const int wn0 = (w % WN_) * 32, wm0 = (w / WN_) * 64;
    const int m0 = blockIdx.y * BM, n0 = blockIdx.x * BN;

    auto load_stage = [&](int s, int k0) {
#pragma unroll
        for (int i = 0; i < (BM + BN) * 4 / 256; i++) {
            int q = i * 256 + tid;
            const __half* src;
            uint32_t dst;
            if (q < BM * 4) {
                int r = q >> 2, c = q & 3;
                src = A + (size_t)(m0 + r) * Kc + k0 + c * 8;
                dst = smem_u32_of(&sA[s][r][c * 8]);
            } else {
                int q2 = q - BM * 4, r = q2 >> 2, c = q2 & 3;
                src = Bw + (size_t)(n0 + r) * Kc + k0 + c * 8;
                dst = smem_u32_of(&sB[s][r][c * 8]);
            }
            asm volatile("cp.async.cg.shared.global [%0], [%1], 16;" :: "r"(dst), "l"(src));
        }
        asm volatile("cp.async.commit_group;");
    };

    float acc[MF][4][4] = {};
    const int arow = (lane & 7) + ((lane >> 3) & 1) * 8;
    const int akm  = (lane >> 4) & 1;
    const int brow = lane & 7;
    const int bkm  = (lane >> 3) & 1;

    const int NIT = Kc >> 5;
    load_stage(0, 0);
    for (int it = 0; it < NIT; it++) {
        if (it + 1 < NIT) {
            load_stage((it + 1) & 1, (it + 1) * 32);
            asm volatile("cp.async.wait_group 1;");
        } else {
            asm volatile("cp.async.wait_group 0;");
        }
        __syncthreads();
        int s = it & 1;
#pragma unroll
        for (int ks = 0; ks < 2; ks++) {
            uint32_t aR[MF][4], bR[4][2];
#pragma unroll
            for (int ni = 0; ni < 4; ni++) {
                uint32_t ad = smem_u32_of(&sB[s][wn0 + ni * 8 + brow][ks * 16 + bkm * 8]);
                asm volatile("ldmatrix.sync.aligned.m8n8.x2.shared.b16 {%0,%1}, [%2];"
                             : "=r"(bR[ni][0]), "=r"(bR[ni][1]) : "r"(ad));
            }
#pragma unroll
            for (int mi = 0; mi < MF; mi++) {
                uint32_t ad = smem_u32_of(&sA[s][wm0 + mi * 16 + arow][ks * 16 + akm * 8]);
                asm volatile("ldmatrix.sync.aligned.m8n8.x4.shared.b16 {%0,%1,%2,%3}, [%4];"
                             : "=r"(aR[mi][0]), "=r"(aR[mi][1]), "=r"(aR[mi][2]), "=r"(aR[mi][3])
                             : "r"(ad));
            }
#pragma unroll
            for (int mi = 0; mi < MF; mi++)
#pragma unroll
                for (int ni = 0; ni < 4; ni++)
                    asm volatile(
                        "mma.sync.aligned.m16n8k16.row.col.f32.f16.f16.f32 "
                        "{%0,%1,%2,%3}, {%4,%5,%6,%7}, {%8,%9}, {%0,%1,%2,%3};"
                        : "+f"(acc[mi][ni][0]), "+f"(acc[mi][ni][1]),
                          "+f"(acc[mi][ni][2]), "+f"(acc[mi][ni][3])
                        : "r"(aR[mi][0]), "r"(aR[mi][1]), "r"(aR[mi][2]), "r"(aR[mi][3]),
                          "r"(bR[ni][0]), "r"(bR[ni][1]));
        }
        __syncthreads();
    }
#pragma unroll
    for (int mi = 0; mi < MF; mi++) {
#pragma unroll
        for (int half = 0; half < 2; half++) {
            int r = m0 + wm0 + mi * 16 + (lane >> 2) + half * 8;
            size_t dr = (size_t)(r & (NL - 1)) * NB + (size_t)(r >> 7);
#pragma unroll
            for (int ni = 0; ni < 4; ni++) {
                int col = n0 + wn0 + ni * 8 + (lane & 3) * 2;
                *reinterpret_cast<float2*>(&g_P[dr * NG + col]) =
                    make_float2(acc[mi][ni][half * 2 + 0] + g_bvp[col],
                                acc[mi][ni][half * 2 + 1] + g_bvp[col + 1]);
            }
        }
    }
}

// ===================== persistent scan kernel ===============================
// R8 structure: grid (32 n-tiles of 64, 4 m-groups of 64), atomic barrier.
// + cell state in registers, + P(t+1) prefetch before barrier.
static constexpr int SBP = 520;                        // halves (1040 B pitch)
static constexpr int SAP = 136;                        // halves (272 B pitch)
static constexpr int SA_STAGE = 64 * SAP;
static constexpr int SCAN_SMEM = (64 * SBP + 4 * SA_STAGE) * 2;   // 136,192 B

__device__ __forceinline__ void wait_grp(int n) {
    switch (n) {
        case 0: asm volatile("cp.async.wait_group 0;" ::: "memory"); break;
        case 1: asm volatile("cp.async.wait_group 1;" ::: "memory"); break;
        case 2: asm volatile("cp.async.wait_group 2;" ::: "memory"); break;
        default: asm volatile("cp.async.wait_group 3;" ::: "memory"); break;
    }
}

__global__ __launch_bounds__(256)
void scan_kernel(float* __restrict__ out) {
    extern __shared__ __half sm16[];
    __half* sB = sm16;                                // [64][520]
    __half* sA = sm16 + 64 * SBP;                     // [4][64][136]
    const int tid = threadIdx.x, lane = tid & 31, w = tid >> 5;
    const int n0 = blockIdx.x * 64, m0 = blockIdx.y * 64, grp = blockIdx.y;
    const int wn0 = (w & 1) * 32, wm0 = (w >> 1) * 16;

    // ---- resident B tile: W1 rows n0..n0+63, 512 cols ----------------------
#pragma unroll
    for (int i = 0; i < 16; i++) {
        int q = i * 256 + tid;                        // 4096 16B-chunks
        int r = q >> 6, cc = q & 63;
        asm volatile("cp.async.cg.shared.global [%0], [%1], 16;"
                     :: "r"(smem_u32_of(sB + r * SBP + cc * 8)),
                        "l"(g_Wp16 + (size_t)(n0 + r) * NH + cc * 8));
    }
    asm volatile("cp.async.commit_group;");
    asm volatile("cp.async.wait_group 0;");
    __syncthreads();

    const int arow = (lane & 7) + ((lane >> 3) & 1) * 8;
    const int akm  = (lane >> 4) & 1;
    const int browB = ((lane >> 4) & 1) * 8 + (lane & 7);
    const int bkmB  = (lane >> 3) & 1;
    const int p0 = (lane & 3) * 2;
    const int j = ((n0 + wn0) >> 5) * 8 + p0;         // hidden unit (even)

    float creg[2][2] = {};                            // cell state in registers
    float2 pv[2][4];                                  // prefetched P

    auto loadP = [&](int tt) {
        const float* Pt = g_P + (size_t)tt * NB * NG;
#pragma unroll
        for (int half = 0; half < 2; half++) {
            int b = m0 + wm0 + (lane >> 2) + half * 8;
#pragma unroll
            for (int ni = 0; ni < 4; ni++)
                pv[half][ni] = __ldg(reinterpret_cast<const float2*>(
                    Pt + (size_t)b * NG + n0 + wn0 + ni * 8 + p0));
        }
    };
    loadP(0);

    for (int t = 0; t < NL; t++) {
        const int par = t & 1;
        const __half* hsrc = g_h16[par];

        // issue ALL 4 A chunks (16 KB each) immediately
#pragma unroll
        for (int c = 0; c < 4; c++) {
#pragma unroll
            for (int i = 0; i < 4; i++) {
                int q = i * 256 + tid;
                int r = q >> 4, cc = q & 15;
                asm volatile("cp.async.cg.shared.global [%0], [%1], 16;"
                             :: "r"(smem_u32_of(sA + c * SA_STAGE + r * SAP + cc * 8)),
                                "l"(hsrc + (size_t)(m0 + r) * NH + c * 128 + cc * 8));
            }
            asm volatile("cp.async.commit_group;");
        }

        float acc[4][4] = {};
#pragma unroll
        for (int c = 0; c < 4; c++) {
            wait_grp(3 - c);
            __syncthreads();
            const __half* As = sA + c * SA_STAGE;
            const int kb = c * 128;
#pragma unroll
            for (int ks = 0; ks < 8; ks++) {
                uint32_t aR[4];
                asm volatile("ldmatrix.sync.aligned.m8n8.x4.shared.b16 {%0,%1,%2,%3}, [%4];"
                             : "=r"(aR[0]), "=r"(aR[1]), "=r"(aR[2]), "=r"(aR[3])
                             : "r"(smem_u32_of(As + (wm0 + arow) * SAP + ks * 16 + akm * 8)));
#pragma unroll
                for (int p = 0; p < 2; p++) {
                    uint32_t b4[4];
                    asm volatile("ldmatrix.sync.aligned.m8n8.x4.shared.b16 {%0,%1,%2,%3}, [%4];"
                                 : "=r"(b4[0]), "=r"(b4[1]), "=r"(b4[2]), "=r"(b4[3])
                                 : "r"(smem_u32_of(sB + (wn0 + p * 16 + browB) * SBP
                                                   + kb + ks * 16 + bkmB * 8)));
                    asm volatile(
                        "mma.sync.aligned.m16n8k16.row.col.f32.f16.f16.f32 "
                        "{%0,%1,%2,%3}, {%4,%5,%6,%7}, {%8,%9}, {%0,%1,%2,%3};"
                        : "+f"(acc[2 * p][0]), "+f"(acc[2 * p][1]),
                          "+f"(acc[2 * p][2]), "+f"(acc[2 * p][3])
                        : "r"(aR[0]), "r"(aR[1]), "r"(aR[2]), "r"(aR[3]),
                          "r"(b4[0]), "r"(b4[1]));
                    asm volatile(
                        "mma.sync.aligned.m16n8k16.row.col.f32.f16.f16.f32 "
                        "{%0,%1,%2,%3}, {%4,%5,%6,%7}, {%8,%9}, {%0,%1,%2,%3};"
                        : "+f"(acc[2 * p + 1][0]), "+f"(acc[2 * p + 1][1]),
                          "+f"(acc[2 * p + 1][2]), "+f"(acc[2 * p + 1][3])
                        : "r"(aR[0]), "r"(aR[1]), "r"(aR[2]), "r"(aR[3]),
                          "r"(b4[2]), "r"(b4[3]));
                }
            }
        }

        // ---- fused LSTM pointwise epilogue (cell state in registers) -------
        __half* hdst = g_h16[par ^ 1];
#pragma unroll
        for (int half = 0; half < 2; half++) {
            int b = m0 + wm0 + (lane >> 2) + half * 8;
            float hn[2], cn[2];
#pragma unroll
            for (int e = 0; e < 2; e++) {
                int a = half * 2 + e;
                float iv = acc[0][a] + (e ? pv[half][0].y : pv[half][0].x);
                float fv = acc[1][a] + (e ? pv[half][1].y : pv[half][1].x);
                float gv = acc[2][a] + (e ? pv[half][2].y : pv[half][2].x);
                float ov = acc[3][a] + (e ? pv[half][3].y : pv[half][3].x);
                float si = 1.f / (1.f + expf(-iv));
                float sf = 1.f / (1.f + expf(-fv));
                float so = 1.f / (1.f + expf(-ov));
                float tg = tanhf(gv);
                float Cn = sf * creg[half][e] + si * tg;
                creg[half][e] = Cn;
                cn[e] = Cn;
                hn[e] = so * tanhf(Cn);
            }
            size_t o = (size_t)b * (NL * NH) + (size_t)t * NH + j;
            *reinterpret_cast<float2*>(&out[o]) = make_float2(hn[0], hn[1]);
            *reinterpret_cast<float2*>(&out[o + (size_t)NB * NL * NH]) = make_float2(cn[0], cn[1]);
            *reinterpret_cast<__half2*>(hdst + (size_t)b * NH + j) =
                __halves2half2(__float2half_rn(hn[0]), __float2half_rn(hn[1]));
        }

        // prefetch P for next step — overlaps fence + barrier wait
        if (t + 1 < NL) loadP(t + 1);

        // ---- per-m-group barrier ------------------------------------------
        __threadfence();
        __syncthreads();
        if (tid == 0) {
            atomicAdd(&g_bar[grp], 1);
            int target = 32 * (t + 1);
            while (*((volatile int*)&g_bar[grp]) < target) __nanosleep(32);
        }
        __syncthreads();
    }
}

// ===================== x_tilde ==============================================
__global__ void xtilde_kernel(const float* __restrict__ x, const float* __restrict__ Wa,
                              const float* __restrict__ ba, float* __restrict__ out) {
    __shared__ float red[NC];
    __shared__ float s_wa[NL];
    int b = blockIdx.x, c = threadIdx.x;
    if (c < NL) s_wa[c] = Wa[2 * NH + c];
    __syncthreads();
    const float* xb = x + (size_t)b * NL * NC;
    float s = ba[0];
#pragma unroll 4
    for (int l = 0; l < NL; l++) s = fmaf(xb[(size_t)l * NC + c], s_wa[l], s);
    red[c] = s; __syncthreads();
    for (int o = NC / 2; o > 0; o >>= 1) { if (c < o) red[c] = fmaxf(red[c], red[c + o]); __syncthreads(); }
    float mx = red[0]; __syncthreads();
    float e = expf(s - mx);
    red[c] = e; __syncthreads();
    for (int o = NC / 2; o > 0; o >>= 1) { if (c < o) red[c] += red[c + o]; __syncthreads(); }
    float alpha = e / red[0];
    float* ob = out + (size_t)b * NL * NC;
#pragma unroll 4
    for (int l = 0; l < NL; l++) ob[(size_t)l * NC + c] = alpha * xb[(size_t)l * NC + c];
}

// ===================== host =================================================
extern "C" void kernel_launch(void* const* d_in, const int* in_sizes, int n_in,
                              void* d_out, int out_size) {
    const float* x   = (const float*)d_in[0];
    const float* Wih = (const float*)d_in[1];
    const float* bih = (const float*)d_in[2];
    const float* Wmx = (const float*)d_in[3];
    const float* bmx = (const float*)d_in[4];
    const float* Wmh = (const float*)d_in[5];
    const float* bmh = (const float*)d_in[6];
    const float* Whm = (const float*)d_in[7];
    const float* bhm = (const float*)d_in[8];
    const float* Wa  = (const float*)d_in[9];
    const float* ba  = (const float*)d_in[10];
    float* out = (float*)d_out;

    float *pWp, *pWb;
    __half *pWp16, *pWb16, *pX16;
    cudaGetSymbolAddress((void**)&pWp,   g_Wp);
    cudaGetSymbolAddress((void**)&pWb,   g_Wb);
    cudaGetSymbolAddress((void**)&pWp16, g_Wp16);
    cudaGetSymbolAddress((void**)&pWb16, g_Wb16);
    cudaGetSymbolAddress((void**)&pX16,  g_x16);

    cudaFuncSetAttribute(scan_kernel, cudaFuncAttributeMaxDynamicSharedMemorySize, SCAN_SMEM);

    init_state_kernel<<<(NB * NH + 255) / 256, 256>>>();

    // folded weights (fp32 SIMT — small)
    gemm64<false><<<dim3(NG / 64, NH / 64), 256>>>(Wmh, Whm, nullptr, pWp, NH, NG, NH);
    gemm64<true ><<<dim3(NG / 64, NC / 64), 256>>>(Wmx, Whm, Wih, pWb, NC, NG, NH);
    bvec_kernel<<<dim3(8, 8), 256>>>(bih, bhm, bmx, bmh, Whm);

    // weight / x conversions to fp16
    wsplit16_kernel<<<dim3(NG / 32, NH / 32), 256>>>(pWp, pWp16, NH);
    wsplit16_kernel<<<dim3(NG / 32, NC / 32), 256>>>(pWb, pWb16, NC);
    xsplit_kernel<<<(NB * NL * NC / 4) / 256, 256>>>(x);

    // P = x @ Wbig + bias  (HMMA fp16, Kc=256, time-major output)
    pgemm_mma<<<dim3(NG / 128, (NB * NL) / 128), 256>>>(pX16, pWb16, NC);

    // x_tilde (softmax over c is time-invariant)
    xtilde_kernel<<<NB, 256>>>(x, Wa, ba, out + (size_t)2 * NB * NL * NH);

    // persistent fused scan: R8 structure + creg + P-prefetch
    scan_kernel<<<dim3(32, 4), 256, SCAN_SMEM>>>(out);
}